// round 9
// baseline (speedup 1.0000x reference)
#include <cuda_runtime.h>
#include <cuda_bf16.h>
#include <cstdint>
#include <math.h>

#define Bb 128
#define Tt 512
#define Ee 256
#define Hh 128
#define FOURH 512
#define Vv 32000
#define KP 768

typedef unsigned long long u64t;
typedef __nv_bfloat16 bf16;

// ---------------- static scratch ----------------
__device__ float g_xw[(size_t)2 * Tt * Bb * FOURH];      // [dir][t*128+b][4H]
__device__ __align__(16) bf16 g_ehi[(size_t)Vv * Ee];
__device__ __align__(16) bf16 g_elo[(size_t)Vv * Ee];
__device__ __align__(16) bf16 g_Wt[2][KP][FOURH];        // [dir][k'][n]

// ---------------- helpers ----------------
__device__ __forceinline__ u64t pk2(float lo, float hi) {
    u64t r; asm("mov.b64 %0, {%1, %2};" : "=l"(r) : "f"(lo), "f"(hi)); return r;
}
__device__ __forceinline__ void upk2(u64t v, float& lo, float& hi) {
    asm("mov.b64 {%0, %1}, %2;" : "=f"(lo), "=f"(hi) : "l"(v));
}
#define FFMA2(acc, a, b) asm("fma.rn.f32x2 %0, %1, %2, %0;" : "+l"(acc) : "l"(a), "l"(b))
__device__ __forceinline__ float sigmoid_f(float x) { return __fdividef(1.0f, 1.0f + __expf(-x)); }
__device__ __forceinline__ float tanh_f(float x)    { return __fdividef(2.0f, 1.0f + __expf(-2.0f * x)) - 1.0f; }
__device__ __forceinline__ uint32_t smem_u32(const void* p) {
    uint32_t a;
    asm("{ .reg .u64 t; cvta.to.shared.u64 t, %1; cvt.u32.u64 %0, t; }" : "=r"(a) : "l"(p));
    return a;
}
__device__ __forceinline__ void st_cluster_u64(uint32_t laddr, int rank, u64t v) {
    asm volatile(
        "{ .reg .b32 ra; mapa.shared::cluster.u32 ra, %0, %1; "
        "st.shared::cluster.b64 [ra], %2; }"
        :: "r"(laddr), "r"(rank), "l"(v) : "memory");
}
__device__ __forceinline__ void mbar_arrive_rel(uint32_t laddr, int rank) {
    asm volatile(
        "{ .reg .b32 ra; mapa.shared::cluster.u32 ra, %0, %1; "
        "mbarrier.arrive.release.cluster.shared::cluster.b64 _, [ra]; }"
        :: "r"(laddr), "r"(rank) : "memory");
}
__device__ __forceinline__ void mbar_wait_acq(uint32_t mb, uint32_t parity) {
    asm volatile(
        "{\n\t.reg .pred P1;\n\t"
        "WL_%=:\n\t"
        "mbarrier.try_wait.parity.acquire.cluster.shared::cta.b64 P1, [%0], %1, 0x989680;\n\t"
        "@P1 bra.uni WD_%=;\n\t"
        "bra.uni WL_%=;\n\t"
        "WD_%=:\n\t}" :: "r"(mb), "r"(parity) : "memory");
}
#define MBAR_INIT(a, n) \
    asm volatile("mbarrier.init.shared.b64 [%0], %1;" :: "r"(a), "r"((uint32_t)(n)) : "memory")
#define CLUSTER_SYNC() do { \
    asm volatile("barrier.cluster.arrive.aligned;" ::: "memory"); \
    asm volatile("barrier.cluster.wait.aligned;" ::: "memory"); \
} while (0)

#define LDSM_X4(r0, r1, r2, r3, addr) \
    asm volatile("ldmatrix.sync.aligned.m8n8.x4.shared.b16 {%0,%1,%2,%3}, [%4];" \
                 : "=r"(r0), "=r"(r1), "=r"(r2), "=r"(r3) : "r"(addr))
#define LDSM_X4T(r0, r1, r2, r3, addr) \
    asm volatile("ldmatrix.sync.aligned.m8n8.x4.trans.shared.b16 {%0,%1,%2,%3}, [%4];" \
                 : "=r"(r0), "=r"(r1), "=r"(r2), "=r"(r3) : "r"(addr))
#define MMA16816(c, a, b0, b1) \
    asm volatile("mma.sync.aligned.m16n8k16.row.col.f32.bf16.bf16.f32 " \
                 "{%0,%1,%2,%3}, {%4,%5,%6,%7}, {%8,%9}, {%0,%1,%2,%3};" \
                 : "+f"((c)[0]), "+f"((c)[1]), "+f"((c)[2]), "+f"((c)[3]) \
                 : "r"((a)[0]), "r"((a)[1]), "r"((a)[2]), "r"((a)[3]), "r"(b0), "r"(b1))

// ---------------- conversion kernels ----------------
__global__ void conv_emb(const float* __restrict__ emb) {
    size_t i = (size_t)blockIdx.x * 256 + threadIdx.x;
    if (i < (size_t)Vv * Ee) {
        float x = emb[i];
        bf16 h = __float2bfloat16(x);
        g_ehi[i] = h;
        g_elo[i] = __float2bfloat16(x - __bfloat162float(h));
    }
}
__global__ void conv_w(const float* __restrict__ Wfw, const float* __restrict__ Wbw) {
    int i = blockIdx.x * 256 + threadIdx.x;
    if (i < 2 * KP * FOURH) {
        int d  = i / (KP * FOURH);
        int r  = i % (KP * FOURH);
        int kp = r / FOURH, n = r % FOURH;
        const float* W = d ? Wbw : Wfw;
        float x = W[(size_t)(kp & 255) * FOURH + n];
        bf16 hv = __float2bfloat16(x);
        g_Wt[d][kp][n] = (kp >= 256 && kp < 512)
                             ? __float2bfloat16(x - __bfloat162float(hv)) : hv;
    }
}

// ---------------- mma.sync projection GEMM (unchanged) ----------------
#define ASTR 40
#define BSTR 136

__global__ __launch_bounds__(256)
void proj_mma(const int* __restrict__ tokens) {
    __shared__ __align__(16) bf16 A_sm[128 * ASTR];
    __shared__ __align__(16) bf16 B_sm[32 * BSTR];
    __shared__ int tok[128];

    const int tid = threadIdx.x;
    const int wid = tid >> 5, lane = tid & 31;
    const int wm = wid & 3, wn = wid >> 2;
    const int n0 = blockIdx.x * 128;
    const int m0 = blockIdx.y * 128;
    const int dir = blockIdx.z;

    if (tid < 128) {
        int row = m0 + tid;
        tok[tid] = tokens[(row & 127) * Tt + (row >> 7)];
    }
    const uint32_t sbA = smem_u32(A_sm);
    const uint32_t sbB = smem_u32(B_sm);

    float c[2][8][4];
#pragma unroll
    for (int i = 0; i < 2; i++)
#pragma unroll
        for (int j = 0; j < 8; j++)
#pragma unroll
            for (int q = 0; q < 4; q++) c[i][j][q] = 0.0f;

    __syncthreads();

    for (int kt = 0; kt < 24; kt++) {
        const int kp0 = kt * 32;
        const bf16* __restrict__ Asrc = (kp0 < 512) ? g_ehi : g_elo;
        const int kb = kp0 & 255;

        uint4 av[2], bv[2];
#pragma unroll
        for (int u = 0; u < 2; u++) {
            const int q = tid + u * 256;
            const int arow = q >> 2, ac8 = q & 3;
            av[u] = *(const uint4*)(Asrc + (size_t)tok[arow] * Ee + kb + ac8 * 8);
            const int brow = q >> 4, bn8 = q & 15;
            bv[u] = *(const uint4*)(&g_Wt[dir][kp0 + brow][n0 + bn8 * 8]);
        }
        __syncthreads();
#pragma unroll
        for (int u = 0; u < 2; u++) {
            const int q = tid + u * 256;
            const int arow = q >> 2, ac8 = q & 3;
            *(uint4*)(A_sm + arow * ASTR + ac8 * 8) = av[u];
            const int brow = q >> 4, bn8 = q & 15;
            *(uint4*)(B_sm + brow * BSTR + bn8 * 8) = bv[u];
        }
        __syncthreads();

#pragma unroll
        for (int ks = 0; ks < 2; ks++) {
            uint32_t a[2][4];
#pragma unroll
            for (int i = 0; i < 2; i++) {
                const int m = wm * 32 + i * 16 + (lane & 7) + ((lane >> 3) & 1) * 8;
                const int kc = ks * 16 + (lane >> 4) * 8;
                LDSM_X4(a[i][0], a[i][1], a[i][2], a[i][3],
                        sbA + (uint32_t)(m * ASTR + kc) * 2);
            }
            uint32_t b[4][4];
#pragma unroll
            for (int j2 = 0; j2 < 4; j2++) {
                const int k = ks * 16 + (lane & 7) + ((lane >> 3) & 1) * 8;
                const int n = wn * 64 + j2 * 16 + (lane >> 4) * 8;
                LDSM_X4T(b[j2][0], b[j2][1], b[j2][2], b[j2][3],
                         sbB + (uint32_t)(k * BSTR + n) * 2);
            }
#pragma unroll
            for (int i = 0; i < 2; i++)
#pragma unroll
                for (int j = 0; j < 8; j++)
                    MMA16816(c[i][j], a[i], b[j >> 1][(j & 1) * 2], b[j >> 1][(j & 1) * 2 + 1]);
        }
    }

    const int g = lane >> 2, t2 = (lane & 3) * 2;
    float* const base = g_xw + (size_t)dir * Tt * Bb * FOURH;
#pragma unroll
    for (int i = 0; i < 2; i++) {
        const int mrow = m0 + wm * 32 + i * 16 + g;
#pragma unroll
        for (int j = 0; j < 8; j++) {
            const int col = n0 + wn * 64 + j * 8 + t2;
            float* d0 = base + (size_t)mrow * FOURH + col;
            d0[0] = c[i][j][0]; d0[1] = c[i][j][1];
            float* d1 = d0 + 8 * FOURH;
            d1[0] = c[i][j][2]; d1[1] = c[i][j][3];
        }
    }
}

// ---------------- persistent LSTM: cluster(2), 256 thr, 64 units/CTA ----------------
// 64 CTAs: dir = bx>>5; id = bx&31; btile = id>>1 (8 batch rows); uhalf = id&1.
// Thread: ju = (tid>>5)*8 + ((tid&31)>>2) in 0..63, bpair = tid&3.
// Each thread: 1 unit x 2 batch rows, full k=128 dot (two f32x2 accumulators).
#define HPAD 10
#define U2_OFF 64
#define U2_BYTES (128 * 64 * 16)                 // 128KB
#define HBUF_OFF (U2_OFF + U2_BYTES)
#define HBUF_U64 (128 * HPAD)
#define LSTM_SMEM (HBUF_OFF + 2 * HBUF_U64 * 8)

__global__ __launch_bounds__(256, 1) __cluster_dims__(2, 1, 1)
void lstm_kernel(const float* __restrict__ Ufw, const float* __restrict__ Ubw,
                 const float* __restrict__ bfw, const float* __restrict__ bbw,
                 float* __restrict__ out) {
    extern __shared__ char smem_raw[];
    ulonglong2 (*U2)[64] = (ulonglong2(*)[64])(smem_raw + U2_OFF);
    u64t* hbuf = (u64t*)(smem_raw + HBUF_OFF);
    const uint32_t sbase = smem_u32(smem_raw);
    const uint32_t hbase = sbase + HBUF_OFF;

    const int bx = blockIdx.x;
    const int dir = bx >> 5, id = bx & 31;
    const int btile = id >> 1, uhalf = id & 1;
    const int tid = threadIdx.x;
    const int lane = tid & 31;
    const int ju = ((tid >> 5) << 3) + (lane >> 2);   // 0..63
    const int bpair = lane & 3;
    const int j = uhalf * 64 + ju;                    // global unit 0..127
    const int bl0 = bpair * 2;
    const int b0 = btile * 8 + bl0, b1 = b0 + 1;
    const int peer = 1 - (int)(bx & 1);               // cluster rank of peer

    const float* __restrict__ U    = dir ? Ubw : Ufw;
    const float* __restrict__ bias = dir ? bbw : bfw;

    // U2[k][m]: gate pairs {pk(Ui,Uf), pk(Ug,Uo)} for unit (uhalf*64+m)
    for (int idx = tid; idx < 128 * 64; idx += 256) {
        const int k = idx >> 6, m = idx & 63;
        const float* up = U + (size_t)k * FOURH + uhalf * 64 + m;
        ulonglong2 v;
        v.x = pk2(up[0],   up[128]);
        v.y = pk2(up[256], up[384]);
        U2[k][m] = v;
    }
    for (int q = tid; q < 2 * HBUF_U64; q += 256) hbuf[q] = 0ull;
    if (tid == 0) { MBAR_INIT(sbase, 2); MBAR_INIT(sbase + 8, 2); }

    const u64t bz01 = pk2(bias[j], bias[Hh + j]);
    const u64t bz23 = pk2(bias[2 * Hh + j], bias[3 * Hh + j]);

    __syncthreads();
    CLUSTER_SYNC();   // peer's mbars + zeroed buffers visible

    float c0 = 0.0f, c1 = 0.0f, hout0 = 0.0f, hout1 = 0.0f;
    const size_t xw_dir = (size_t)dir * ((size_t)Tt * Bb * FOURH);
    const uint32_t hoff0 = (uint32_t)((j * HPAD + bl0) * 8);
    const uint32_t hoff1 = hoff0 + 8u;
    const uint32_t bufB = (uint32_t)(HBUF_U64 * 8);
    uint32_t ph0 = 0, ph1 = 0;

    for (int t = 0; t < Tt; t++) {
        const int tt = dir ? (Tt - 1 - t) : t;
        const int p = t & 1;
        const u64t* __restrict__ hrd = hbuf + (size_t)p * HBUF_U64;

        // xw prefetch BEFORE the wait — DRAM latency overlaps the sync
        const float* xwp = g_xw + xw_dir + ((size_t)tt * Bb) * FOURH;
        const float x00 = __ldg(xwp + (size_t)b0 * FOURH + j);
        const float x01 = __ldg(xwp + (size_t)b0 * FOURH + Hh + j);
        const float x02 = __ldg(xwp + (size_t)b0 * FOURH + 2 * Hh + j);
        const float x03 = __ldg(xwp + (size_t)b0 * FOURH + 3 * Hh + j);
        const float x10 = __ldg(xwp + (size_t)b1 * FOURH + j);
        const float x11 = __ldg(xwp + (size_t)b1 * FOURH + Hh + j);
        const float x12 = __ldg(xwp + (size_t)b1 * FOURH + 2 * Hh + j);
        const float x13 = __ldg(xwp + (size_t)b1 * FOURH + 3 * Hh + j);

        if (t > 0) {
            if (p == 0) { mbar_wait_acq(sbase, ph0); ph0 ^= 1; }
            else        { mbar_wait_acq(sbase + 8, ph1); ph1 ^= 1; }
        }

        u64t acc01_0 = bz01, acc23_0 = bz23;
        u64t acc01_1 = bz01, acc23_1 = bz23;
#pragma unroll 16
        for (int k = 0; k < 128; k++) {
            const ulonglong2 u = U2[k][ju];
            const ulonglong2 hh = *(const ulonglong2*)(hrd + k * HPAD + bl0);
            FFMA2(acc01_0, hh.x, u.x);
            FFMA2(acc23_0, hh.x, u.y);
            FFMA2(acc01_1, hh.y, u.x);
            FFMA2(acc23_1, hh.y, u.y);
        }

        float a00, a01, a02, a03, a10, a11, a12, a13;
        upk2(acc01_0, a00, a01); upk2(acc23_0, a02, a03);
        upk2(acc01_1, a10, a11); upk2(acc23_1, a12, a13);
        a00 += x00; a01 += x01; a02 += x02; a03 += x03;
        a10 += x10; a11 += x11; a12 += x12; a13 += x13;
        {
            const float ig = sigmoid_f(a00), fg = sigmoid_f(a01);
            const float gg = tanh_f(a02), og = sigmoid_f(a03);
            c0 = fg * c0 + ig * gg;
            hout0 = og * tanh_f(c0);
        }
        {
            const float ig = sigmoid_f(a10), fg = sigmoid_f(a11);
            const float gg = tanh_f(a12), og = sigmoid_f(a13);
            c1 = fg * c1 + ig * gg;
            hout1 = og * tanh_f(c1);
        }

        // publish h into buffer p^1: local STS + one remote DSMEM store
        {
            const uint32_t wb = hbase + (p ? 0u : bufB);
            const u64t v0 = pk2(hout0, hout0);
            const u64t v1 = pk2(hout1, hout1);
            u64t* lw = (u64t*)((char*)hbuf + (p ? 0u : bufB));
            lw[j * HPAD + bl0]     = v0;
            lw[j * HPAD + bl0 + 1] = v1;
            st_cluster_u64(wb + hoff0, peer, v0);
            st_cluster_u64(wb + hoff1, peer, v1);
        }
        __syncthreads();           // all local+remote stores issued & ordered
        if (tid < 2) {
            const uint32_t mb = sbase + (uint32_t)((p ^ 1) * 8);
            mbar_arrive_rel(mb, tid);   // arrive on both ranks' mbar[p^1]
        }
        // out stores in the shadow of the peer's sync
        out[((size_t)b0 * Tt + tt) * 256 + dir * Hh + j] = hout0;
        out[((size_t)b1 * Tt + tt) * 256 + dir * Hh + j] = hout1;
    }

    const size_t fin = (size_t)Bb * Tt * 256 + (size_t)dir * 2 * Bb * Hh;
    out[fin + (size_t)b0 * Hh + j] = hout0;
    out[fin + (size_t)b1 * Hh + j] = hout1;
    out[fin + Bb * Hh + (size_t)b0 * Hh + j] = c0;
    out[fin + Bb * Hh + (size_t)b1 * Hh + j] = c1;

    CLUSTER_SYNC();   // no CTA exits while the peer may still DSMEM-write here
}

// ---------------- launch ----------------
extern "C" void kernel_launch(void* const* d_in, const int* in_sizes, int n_in,
                              void* d_out, int out_size) {
    const int*   tokens = (const int*)d_in[0];
    const float* emb    = (const float*)d_in[1];
    const float* Wfw    = (const float*)d_in[2];
    const float* Ufw    = (const float*)d_in[3];
    const float* bfw    = (const float*)d_in[4];
    const float* Wbw    = (const float*)d_in[5];
    const float* Ubw    = (const float*)d_in[6];
    const float* bbw    = (const float*)d_in[7];
    float* out = (float*)d_out;

    static bool attr_set = false;
    if (!attr_set) {
        cudaFuncSetAttribute(lstm_kernel, cudaFuncAttributeMaxDynamicSharedMemorySize, (int)LSTM_SMEM);
        attr_set = true;
    }

    conv_emb<<<(Vv * Ee + 255) / 256, 256>>>(emb);
    conv_w<<<(2 * KP * FOURH + 255) / 256, 256>>>(Wfw, Wbw);
    proj_mma<<<dim3(4, 512, 2), 256>>>(tokens);
    lstm_kernel<<<64, 256, LSTM_SMEM>>>(Ufw, Ubw, bfw, bbw, out);
}

// round 10
// speedup vs baseline: 1.3642x; 1.3642x over previous
#include <cuda_runtime.h>
#include <cuda_bf16.h>
#include <cstdint>
#include <math.h>

#define Bb 128
#define Tt 512
#define Ee 256
#define Hh 128
#define FOURH 512
#define Vv 32000
#define KP 768

typedef unsigned long long u64t;
typedef __nv_bfloat16 bf16;

// ---------------- static scratch ----------------
__device__ float g_xw[(size_t)2 * Tt * Bb * FOURH];      // [dir][t*128+b][4H]
__device__ __align__(16) bf16 g_ehi[(size_t)Vv * Ee];
__device__ __align__(16) bf16 g_elo[(size_t)Vv * Ee];
__device__ __align__(16) bf16 g_Wt[2][KP][FOURH];        // [dir][k'][n]

// ---------------- helpers ----------------
__device__ __forceinline__ u64t pk2(float lo, float hi) {
    u64t r; asm("mov.b64 %0, {%1, %2};" : "=l"(r) : "f"(lo), "f"(hi)); return r;
}
__device__ __forceinline__ void upk2(u64t v, float& lo, float& hi) {
    asm("mov.b64 {%0, %1}, %2;" : "=f"(lo), "=f"(hi) : "l"(v));
}
#define FFMA2(acc, a, b) asm("fma.rn.f32x2 %0, %1, %2, %0;" : "+l"(acc) : "l"(a), "l"(b))
__device__ __forceinline__ float sigmoid_f(float x) { return __fdividef(1.0f, 1.0f + __expf(-x)); }
__device__ __forceinline__ float tanh_f(float x)    { return __fdividef(2.0f, 1.0f + __expf(-2.0f * x)) - 1.0f; }
__device__ __forceinline__ uint32_t smem_u32(const void* p) {
    uint32_t a;
    asm("{ .reg .u64 t; cvta.to.shared.u64 t, %1; cvt.u32.u64 %0, t; }" : "=r"(a) : "l"(p));
    return a;
}
__device__ __forceinline__ void st_cluster_u64(uint32_t laddr, int rank, u64t v) {
    asm volatile(
        "{ .reg .b32 ra; mapa.shared::cluster.u32 ra, %0, %1; "
        "st.shared::cluster.b64 [ra], %2; }"
        :: "r"(laddr), "r"(rank), "l"(v) : "memory");
}
#define CLUSTER_ARRIVE() asm volatile("barrier.cluster.arrive.aligned;" ::: "memory")
#define CLUSTER_WAIT()   asm volatile("barrier.cluster.wait.aligned;" ::: "memory")
#define CLUSTER_SYNC() do { CLUSTER_ARRIVE(); CLUSTER_WAIT(); } while (0)

#define LDSM_X4(r0, r1, r2, r3, addr) \
    asm volatile("ldmatrix.sync.aligned.m8n8.x4.shared.b16 {%0,%1,%2,%3}, [%4];" \
                 : "=r"(r0), "=r"(r1), "=r"(r2), "=r"(r3) : "r"(addr))
#define LDSM_X4T(r0, r1, r2, r3, addr) \
    asm volatile("ldmatrix.sync.aligned.m8n8.x4.trans.shared.b16 {%0,%1,%2,%3}, [%4];" \
                 : "=r"(r0), "=r"(r1), "=r"(r2), "=r"(r3) : "r"(addr))
#define MMA16816(c, a, b0, b1) \
    asm volatile("mma.sync.aligned.m16n8k16.row.col.f32.bf16.bf16.f32 " \
                 "{%0,%1,%2,%3}, {%4,%5,%6,%7}, {%8,%9}, {%0,%1,%2,%3};" \
                 : "+f"((c)[0]), "+f"((c)[1]), "+f"((c)[2]), "+f"((c)[3]) \
                 : "r"((a)[0]), "r"((a)[1]), "r"((a)[2]), "r"((a)[3]), "r"(b0), "r"(b1))

// ---------------- conversion kernels ----------------
__global__ void conv_emb(const float* __restrict__ emb) {
    size_t i = (size_t)blockIdx.x * 256 + threadIdx.x;
    if (i < (size_t)Vv * Ee) {
        float x = emb[i];
        bf16 h = __float2bfloat16(x);
        g_ehi[i] = h;
        g_elo[i] = __float2bfloat16(x - __bfloat162float(h));
    }
}
__global__ void conv_w(const float* __restrict__ Wfw, const float* __restrict__ Wbw) {
    int i = blockIdx.x * 256 + threadIdx.x;
    if (i < 2 * KP * FOURH) {
        int d  = i / (KP * FOURH);
        int r  = i % (KP * FOURH);
        int kp = r / FOURH, n = r % FOURH;
        const float* W = d ? Wbw : Wfw;
        float x = W[(size_t)(kp & 255) * FOURH + n];
        bf16 hv = __float2bfloat16(x);
        g_Wt[d][kp][n] = (kp >= 256 && kp < 512)
                             ? __float2bfloat16(x - __bfloat162float(hv)) : hv;
    }
}

// ---------------- mma.sync projection GEMM (unchanged) ----------------
#define ASTR 40
#define BSTR 136

__global__ __launch_bounds__(256)
void proj_mma(const int* __restrict__ tokens) {
    __shared__ __align__(16) bf16 A_sm[128 * ASTR];
    __shared__ __align__(16) bf16 B_sm[32 * BSTR];
    __shared__ int tok[128];

    const int tid = threadIdx.x;
    const int wid = tid >> 5, lane = tid & 31;
    const int wm = wid & 3, wn = wid >> 2;
    const int n0 = blockIdx.x * 128;
    const int m0 = blockIdx.y * 128;
    const int dir = blockIdx.z;

    if (tid < 128) {
        int row = m0 + tid;
        tok[tid] = tokens[(row & 127) * Tt + (row >> 7)];
    }
    const uint32_t sbA = smem_u32(A_sm);
    const uint32_t sbB = smem_u32(B_sm);

    float c[2][8][4];
#pragma unroll
    for (int i = 0; i < 2; i++)
#pragma unroll
        for (int j = 0; j < 8; j++)
#pragma unroll
            for (int q = 0; q < 4; q++) c[i][j][q] = 0.0f;

    __syncthreads();

    for (int kt = 0; kt < 24; kt++) {
        const int kp0 = kt * 32;
        const bf16* __restrict__ Asrc = (kp0 < 512) ? g_ehi : g_elo;
        const int kb = kp0 & 255;

        uint4 av[2], bv[2];
#pragma unroll
        for (int u = 0; u < 2; u++) {
            const int q = tid + u * 256;
            const int arow = q >> 2, ac8 = q & 3;
            av[u] = *(const uint4*)(Asrc + (size_t)tok[arow] * Ee + kb + ac8 * 8);
            const int brow = q >> 4, bn8 = q & 15;
            bv[u] = *(const uint4*)(&g_Wt[dir][kp0 + brow][n0 + bn8 * 8]);
        }
        __syncthreads();
#pragma unroll
        for (int u = 0; u < 2; u++) {
            const int q = tid + u * 256;
            const int arow = q >> 2, ac8 = q & 3;
            *(uint4*)(A_sm + arow * ASTR + ac8 * 8) = av[u];
            const int brow = q >> 4, bn8 = q & 15;
            *(uint4*)(B_sm + brow * BSTR + bn8 * 8) = bv[u];
        }
        __syncthreads();

#pragma unroll
        for (int ks = 0; ks < 2; ks++) {
            uint32_t a[2][4];
#pragma unroll
            for (int i = 0; i < 2; i++) {
                const int m = wm * 32 + i * 16 + (lane & 7) + ((lane >> 3) & 1) * 8;
                const int kc = ks * 16 + (lane >> 4) * 8;
                LDSM_X4(a[i][0], a[i][1], a[i][2], a[i][3],
                        sbA + (uint32_t)(m * ASTR + kc) * 2);
            }
            uint32_t b[4][4];
#pragma unroll
            for (int j2 = 0; j2 < 4; j2++) {
                const int k = ks * 16 + (lane & 7) + ((lane >> 3) & 1) * 8;
                const int n = wn * 64 + j2 * 16 + (lane >> 4) * 8;
                LDSM_X4T(b[j2][0], b[j2][1], b[j2][2], b[j2][3],
                         sbB + (uint32_t)(k * BSTR + n) * 2);
            }
#pragma unroll
            for (int i = 0; i < 2; i++)
#pragma unroll
                for (int j = 0; j < 8; j++)
                    MMA16816(c[i][j], a[i], b[j >> 1][(j & 1) * 2], b[j >> 1][(j & 1) * 2 + 1]);
        }
    }

    const int g = lane >> 2, t2 = (lane & 3) * 2;
    float* const base = g_xw + (size_t)dir * Tt * Bb * FOURH;
#pragma unroll
    for (int i = 0; i < 2; i++) {
        const int mrow = m0 + wm * 32 + i * 16 + g;
#pragma unroll
        for (int j = 0; j < 8; j++) {
            const int col = n0 + wn * 64 + j * 8 + t2;
            float* d0 = base + (size_t)mrow * FOURH + col;
            d0[0] = c[i][j][0]; d0[1] = c[i][j][1];
            float* d1 = d0 + 8 * FOURH;
            d1[0] = c[i][j][2]; d1[1] = c[i][j][3];
        }
    }
}

// ---------------- persistent LSTM: cluster(4), 256 thr, 1 unit x 1 row ----------------
// 128 CTAs: dir=bx>>6, btile=(bx&63)>>2 (8 rows), utile=bx&3 (32 units).
// Thread: ju = tid>>3 (0..31), bl = tid&7. 2 warps per SMSP hide dot latency.
#define HPAD 10
#define U2_OFF 64
#define U2_BYTES (128 * 32 * 16)                 // 64KB
#define HBUF_OFF (U2_OFF + U2_BYTES)
#define HBUF_U64 (128 * HPAD)
#define LSTM_SMEM (HBUF_OFF + 2 * HBUF_U64 * 8)

__global__ __launch_bounds__(256, 1) __cluster_dims__(4, 1, 1)
void lstm_kernel(const float* __restrict__ Ufw, const float* __restrict__ Ubw,
                 const float* __restrict__ bfw, const float* __restrict__ bbw,
                 float* __restrict__ out) {
    extern __shared__ char smem_raw[];
    ulonglong2 (*U2)[32] = (ulonglong2(*)[32])(smem_raw + U2_OFF);
    u64t* hbuf = (u64t*)(smem_raw + HBUF_OFF);
    const uint32_t hbase = smem_u32(smem_raw) + HBUF_OFF;

    const int bx = blockIdx.x;
    const int dir = bx >> 6, id = bx & 63;
    const int btile = id >> 2, utile = id & 3;
    const int tid = threadIdx.x;
    const int ju = tid >> 3;                // unit local 0..31
    const int bl = tid & 7;                 // batch row local 0..7
    const int j = utile * 32 + ju;          // global unit
    const int b = btile * 8 + bl;           // global batch row

    const float* __restrict__ U    = dir ? Ubw : Ufw;
    const float* __restrict__ bias = dir ? bbw : bfw;

    // U2[k][m]: gate pairs {pk(Ui,Uf), pk(Ug,Uo)} for unit (utile*32+m)
    for (int idx = tid; idx < 128 * 32; idx += 256) {
        const int k = idx >> 5, m = idx & 31;
        const float* up = U + (size_t)k * FOURH + utile * 32 + m;
        ulonglong2 v;
        v.x = pk2(up[0],   up[128]);
        v.y = pk2(up[256], up[384]);
        U2[k][m] = v;
    }
    for (int q = tid; q < 2 * HBUF_U64; q += 256) hbuf[q] = 0ull;

    const u64t bz01 = pk2(bias[j], bias[Hh + j]);
    const u64t bz23 = pk2(bias[2 * Hh + j], bias[3 * Hh + j]);

    __syncthreads();
    CLUSTER_SYNC();   // zeroed buffers visible before any peer DSMEM write

    float c0 = 0.0f, hout0 = 0.0f;
    const size_t xw_dir = (size_t)dir * ((size_t)Tt * Bb * FOURH);
    const uint32_t hoff = (uint32_t)((j * HPAD + bl) * 8);
    const uint32_t bufB = (uint32_t)(HBUF_U64 * 8);

    for (int t = 0; t < Tt; t++) {
        const int tt = dir ? (Tt - 1 - t) : t;
        const int p = t & 1;
        const u64t* __restrict__ hrd = hbuf + (size_t)p * HBUF_U64;

        // xw prefetch BEFORE the wait — DRAM latency overlaps the sync
        const float* xwp = g_xw + xw_dir + ((size_t)tt * Bb + b) * FOURH;
        const float x0 = __ldg(xwp + j);
        const float x1 = __ldg(xwp + Hh + j);
        const float x2 = __ldg(xwp + 2 * Hh + j);
        const float x3 = __ldg(xwp + 3 * Hh + j);

        if (t > 0) CLUSTER_WAIT();

        u64t acc01 = bz01, acc23 = bz23;
#pragma unroll 16
        for (int k = 0; k < 128; k++) {
            const ulonglong2 u = U2[k][ju];
            const u64t hh = hrd[k * HPAD + bl];
            FFMA2(acc01, hh, u.x);
            FFMA2(acc23, hh, u.y);
        }

        float a0, a1, a2, a3;
        upk2(acc01, a0, a1); upk2(acc23, a2, a3);
        a0 += x0; a1 += x1; a2 += x2; a3 += x3;
        {
            const float ig = sigmoid_f(a0), fg = sigmoid_f(a1);
            const float gg = tanh_f(a2),   og = sigmoid_f(a3);
            c0 = fg * c0 + ig * gg;
            hout0 = og * tanh_f(c0);
        }

        // publish duplicated h pair into buffer p^1 of all 4 cluster CTAs
        {
            const uint32_t wb = hbase + (p ? 0u : bufB) + hoff;
            const u64t v0 = pk2(hout0, hout0);
#pragma unroll
            for (int r = 0; r < 4; r++) st_cluster_u64(wb, r, v0);
        }
        if (t < Tt - 1) CLUSTER_ARRIVE();
        // out store in the shadow of peers' arrival
        out[((size_t)b * Tt + tt) * 256 + dir * Hh + j] = hout0;
    }

    const size_t fin = (size_t)Bb * Tt * 256 + (size_t)dir * 2 * Bb * Hh;
    out[fin + (size_t)b * Hh + j]           = hout0;
    out[fin + Bb * Hh + (size_t)b * Hh + j] = c0;

    CLUSTER_SYNC();   // no CTA exits while peers may still DSMEM-write here
}

// ---------------- launch ----------------
extern "C" void kernel_launch(void* const* d_in, const int* in_sizes, int n_in,
                              void* d_out, int out_size) {
    const int*   tokens = (const int*)d_in[0];
    const float* emb    = (const float*)d_in[1];
    const float* Wfw    = (const float*)d_in[2];
    const float* Ufw    = (const float*)d_in[3];
    const float* bfw    = (const float*)d_in[4];
    const float* Wbw    = (const float*)d_in[5];
    const float* Ubw    = (const float*)d_in[6];
    const float* bbw    = (const float*)d_in[7];
    float* out = (float*)d_out;

    static bool attr_set = false;
    if (!attr_set) {
        cudaFuncSetAttribute(lstm_kernel, cudaFuncAttributeMaxDynamicSharedMemorySize, (int)LSTM_SMEM);
        attr_set = true;
    }

    conv_emb<<<(Vv * Ee + 255) / 256, 256>>>(emb);
    conv_w<<<(2 * KP * FOURH + 255) / 256, 256>>>(Wfw, Wbw);
    proj_mma<<<dim3(4, 512, 2), 256>>>(tokens);
    lstm_kernel<<<128, 256, LSTM_SMEM>>>(Ufw, Ubw, bfw, bbw, out);
}

// round 11
// speedup vs baseline: 1.6792x; 1.2310x over previous
#include <cuda_runtime.h>
#include <cuda_bf16.h>
#include <cstdint>
#include <math.h>

#define Bb 128
#define Tt 512
#define Ee 256
#define Hh 128
#define FOURH 512
#define Vv 32000
#define KP 768

typedef unsigned long long u64t;
typedef __nv_bfloat16 bf16;

// ---------------- static scratch ----------------
__device__ float g_xw[(size_t)2 * Tt * Bb * FOURH];      // [dir][t*128+b][4H]
__device__ __align__(16) bf16 g_ehi[(size_t)Vv * Ee];
__device__ __align__(16) bf16 g_elo[(size_t)Vv * Ee];
__device__ __align__(16) bf16 g_Wt[2][KP][FOURH];        // [dir][k'][n]

// ---------------- helpers ----------------
__device__ __forceinline__ float sigmoid_f(float x) { return __fdividef(1.0f, 1.0f + __expf(-x)); }
__device__ __forceinline__ float tanh_f(float x)    { return __fdividef(2.0f, 1.0f + __expf(-2.0f * x)) - 1.0f; }
__device__ __forceinline__ uint32_t smem_u32(const void* p) {
    uint32_t a;
    asm("{ .reg .u64 t; cvta.to.shared.u64 t, %1; cvt.u32.u64 %0, t; }" : "=r"(a) : "l"(p));
    return a;
}
__device__ __forceinline__ void st_cluster_u32(uint32_t laddr, int rank, uint32_t v) {
    asm volatile(
        "{ .reg .b32 ra; mapa.shared::cluster.u32 ra, %0, %1; "
        "st.shared::cluster.b32 [ra], %2; }"
        :: "r"(laddr), "r"(rank), "r"(v) : "memory");
}
__device__ __forceinline__ void st_cluster_u16(uint32_t laddr, int rank, unsigned short v) {
    asm volatile(
        "{ .reg .b32 ra; mapa.shared::cluster.u32 ra, %0, %1; "
        "st.shared::cluster.b16 [ra], %2; }"
        :: "r"(laddr), "r"(rank), "h"(v) : "memory");
}
#define CLUSTER_ARRIVE() asm volatile("barrier.cluster.arrive.aligned;" ::: "memory")
#define CLUSTER_WAIT()   asm volatile("barrier.cluster.wait.aligned;" ::: "memory")
#define CLUSTER_SYNC() do { CLUSTER_ARRIVE(); CLUSTER_WAIT(); } while (0)

#define LDSM_X4(r0, r1, r2, r3, addr) \
    asm volatile("ldmatrix.sync.aligned.m8n8.x4.shared.b16 {%0,%1,%2,%3}, [%4];" \
                 : "=r"(r0), "=r"(r1), "=r"(r2), "=r"(r3) : "r"(addr))
#define LDSM_X4T(r0, r1, r2, r3, addr) \
    asm volatile("ldmatrix.sync.aligned.m8n8.x4.trans.shared.b16 {%0,%1,%2,%3}, [%4];" \
                 : "=r"(r0), "=r"(r1), "=r"(r2), "=r"(r3) : "r"(addr))
#define MMA16816(c, a, b0, b1) \
    asm volatile("mma.sync.aligned.m16n8k16.row.col.f32.bf16.bf16.f32 " \
                 "{%0,%1,%2,%3}, {%4,%5,%6,%7}, {%8,%9}, {%0,%1,%2,%3};" \
                 : "+f"((c)[0]), "+f"((c)[1]), "+f"((c)[2]), "+f"((c)[3]) \
                 : "r"((a)[0]), "r"((a)[1]), "r"((a)[2]), "r"((a)[3]), "r"(b0), "r"(b1))

__device__ __forceinline__ unsigned short bfu(float x) {
    bf16 h = __float2bfloat16(x);
    return __bfloat16_as_ushort(h);
}
__device__ __forceinline__ float bff(unsigned short u) {
    return __bfloat162float(__ushort_as_bfloat16(u));
}

// ---------------- conversion kernels ----------------
__global__ void conv_emb(const float* __restrict__ emb) {
    size_t i = (size_t)blockIdx.x * 256 + threadIdx.x;
    if (i < (size_t)Vv * Ee) {
        float x = emb[i];
        bf16 h = __float2bfloat16(x);
        g_ehi[i] = h;
        g_elo[i] = __float2bfloat16(x - __bfloat162float(h));
    }
}
__global__ void conv_w(const float* __restrict__ Wfw, const float* __restrict__ Wbw) {
    int i = blockIdx.x * 256 + threadIdx.x;
    if (i < 2 * KP * FOURH) {
        int d  = i / (KP * FOURH);
        int r  = i % (KP * FOURH);
        int kp = r / FOURH, n = r % FOURH;
        const float* W = d ? Wbw : Wfw;
        float x = W[(size_t)(kp & 255) * FOURH + n];
        bf16 hv = __float2bfloat16(x);
        g_Wt[d][kp][n] = (kp >= 256 && kp < 512)
                             ? __float2bfloat16(x - __bfloat162float(hv)) : hv;
    }
}

// ---------------- mma.sync projection GEMM (unchanged) ----------------
#define ASTR 40
#define BSTR 136

__global__ __launch_bounds__(256)
void proj_mma(const int* __restrict__ tokens) {
    __shared__ __align__(16) bf16 A_sm[128 * ASTR];
    __shared__ __align__(16) bf16 B_sm[32 * BSTR];
    __shared__ int tok[128];

    const int tid = threadIdx.x;
    const int wid = tid >> 5, lane = tid & 31;
    const int wm = wid & 3, wn = wid >> 2;
    const int n0 = blockIdx.x * 128;
    const int m0 = blockIdx.y * 128;
    const int dir = blockIdx.z;

    if (tid < 128) {
        int row = m0 + tid;
        tok[tid] = tokens[(row & 127) * Tt + (row >> 7)];
    }
    const uint32_t sbA = smem_u32(A_sm);
    const uint32_t sbB = smem_u32(B_sm);

    float c[2][8][4];
#pragma unroll
    for (int i = 0; i < 2; i++)
#pragma unroll
        for (int j = 0; j < 8; j++)
#pragma unroll
            for (int q = 0; q < 4; q++) c[i][j][q] = 0.0f;

    __syncthreads();

    for (int kt = 0; kt < 24; kt++) {
        const int kp0 = kt * 32;
        const bf16* __restrict__ Asrc = (kp0 < 512) ? g_ehi : g_elo;
        const int kb = kp0 & 255;

        uint4 av[2], bv[2];
#pragma unroll
        for (int u = 0; u < 2; u++) {
            const int q = tid + u * 256;
            const int arow = q >> 2, ac8 = q & 3;
            av[u] = *(const uint4*)(Asrc + (size_t)tok[arow] * Ee + kb + ac8 * 8);
            const int brow = q >> 4, bn8 = q & 15;
            bv[u] = *(const uint4*)(&g_Wt[dir][kp0 + brow][n0 + bn8 * 8]);
        }
        __syncthreads();
#pragma unroll
        for (int u = 0; u < 2; u++) {
            const int q = tid + u * 256;
            const int arow = q >> 2, ac8 = q & 3;
            *(uint4*)(A_sm + arow * ASTR + ac8 * 8) = av[u];
            const int brow = q >> 4, bn8 = q & 15;
            *(uint4*)(B_sm + brow * BSTR + bn8 * 8) = bv[u];
        }
        __syncthreads();

#pragma unroll
        for (int ks = 0; ks < 2; ks++) {
            uint32_t a[2][4];
#pragma unroll
            for (int i = 0; i < 2; i++) {
                const int m = wm * 32 + i * 16 + (lane & 7) + ((lane >> 3) & 1) * 8;
                const int kc = ks * 16 + (lane >> 4) * 8;
                LDSM_X4(a[i][0], a[i][1], a[i][2], a[i][3],
                        sbA + (uint32_t)(m * ASTR + kc) * 2);
            }
            uint32_t b[4][4];
#pragma unroll
            for (int j2 = 0; j2 < 4; j2++) {
                const int k = ks * 16 + (lane & 7) + ((lane >> 3) & 1) * 8;
                const int n = wn * 64 + j2 * 16 + (lane >> 4) * 8;
                LDSM_X4T(b[j2][0], b[j2][1], b[j2][2], b[j2][3],
                         sbB + (uint32_t)(k * BSTR + n) * 2);
            }
#pragma unroll
            for (int i = 0; i < 2; i++)
#pragma unroll
                for (int j = 0; j < 8; j++)
                    MMA16816(c[i][j], a[i], b[j >> 1][(j & 1) * 2], b[j >> 1][(j & 1) * 2 + 1]);
        }
    }

    const int g = lane >> 2, t2 = (lane & 3) * 2;
    float* const base = g_xw + (size_t)dir * Tt * Bb * FOURH;
#pragma unroll
    for (int i = 0; i < 2; i++) {
        const int mrow = m0 + wm * 32 + i * 16 + g;
#pragma unroll
        for (int j = 0; j < 8; j++) {
            const int col = n0 + wn * 64 + j * 8 + t2;
            float* d0 = base + (size_t)mrow * FOURH + col;
            d0[0] = c[i][j][0]; d0[1] = c[i][j][1];
            float* d1 = d0 + 8 * FOURH;
            d1[0] = c[i][j][2]; d1[1] = c[i][j][3];
        }
    }
}

// ---------------- persistent LSTM: tensor-core recurrence ----------------
// 128 CTAs, cluster(4) = one (dir,btile). CTA: 8 batch rows x 32 units
// (128 gatecols). Per step: z = h_pad[16,384] @ Ureg[384,128] via mma.sync,
// U held in registers (hi/lo split, K' = [ (hhi,hlo) x Uhi | hhi x Ulo ]).
// h exchanged via DSMEM in bf16 A-layout; R10 arrive/wait cluster protocol.
#define HSTR 784              // A row stride bytes (768 data + 16 pad)
#define NKS 24                // K' = 384 -> 24 k16 steps

__global__ __launch_bounds__(256, 1) __cluster_dims__(4, 1, 1)
void lstm_kernel(const float* __restrict__ Ufw, const float* __restrict__ Ubw,
                 const float* __restrict__ bfw, const float* __restrict__ bbw,
                 float* __restrict__ out) {
    __shared__ float z_sm[8][132];
    __shared__ __align__(16) char hbuf[2][16][HSTR];

    const int bx = blockIdx.x;
    const int dir = bx >> 6, id = bx & 63;
    const int btile = id >> 2, utile = id & 3;
    const int tid = threadIdx.x;
    const int w = tid >> 5, lane = tid & 31;
    const int kq = lane & 3, nq = lane >> 2;
    const int ju = tid >> 3, bl = tid & 7;
    const int j = utile * 32 + ju;          // global unit 0..127
    const int b = btile * 8 + bl;           // global batch row

    const float* __restrict__ U    = dir ? Ubw : Ufw;
    const float* __restrict__ bias = dir ? bbw : bfw;

    // ---- B fragments in registers: breg[ks][tile][2] ----
    uint32_t breg[NKS][2][2];
#pragma unroll
    for (int tile = 0; tile < 2; tile++) {
        const int nloc = w * 16 + tile * 8 + nq;                  // 0..127
        const int gcol = (nloc >> 5) * Hh + utile * 32 + (nloc & 31);
#pragma unroll
        for (int ks = 0; ks < 16; ks++) {      // (hhi,hlo) x dup(Uhi)
            const int u0 = 8 * ks + kq;
            const unsigned short h0 = bfu(U[(size_t)u0 * FOURH + gcol]);
            const unsigned short h1 = bfu(U[(size_t)(u0 + 4) * FOURH + gcol]);
            breg[ks][tile][0] = (uint32_t)h0 | ((uint32_t)h0 << 16);
            breg[ks][tile][1] = (uint32_t)h1 | ((uint32_t)h1 << 16);
        }
#pragma unroll
        for (int ks = 16; ks < NKS; ks++) {    // hhi x Ulo
            const int u0 = 16 * (ks - 16) + 2 * kq;
#pragma unroll
            for (int rr = 0; rr < 2; rr++) {
                const int ua = u0 + rr * 8, ub = ua + 1;
                float va = U[(size_t)ua * FOURH + gcol];
                float vb = U[(size_t)ub * FOURH + gcol];
                unsigned short la = bfu(va - bff(bfu(va)));
                unsigned short lb = bfu(vb - bff(bfu(vb)));
                breg[ks][tile][rr] = (uint32_t)la | ((uint32_t)lb << 16);
            }
        }
    }

    // zero both h buffers (incl. pad rows 8..15, which stay zero)
    for (int q = tid; q < (int)(2 * 16 * HSTR / 4); q += 256)
        ((uint32_t*)hbuf)[q] = 0u;

    const float bz0 = bias[j];
    const float bz1 = bias[Hh + j];
    const float bz2 = bias[2 * Hh + j];
    const float bz3 = bias[3 * Hh + j];

    __syncthreads();
    CLUSTER_SYNC();

    // ldmatrix per-lane source offset within a buffer
    const int arow = (lane & 7) + ((lane >> 3) & 1) * 8;
    const uint32_t rowoff = (uint32_t)(arow * HSTR + (lane >> 4) * 16);
    const uint32_t ab[2] = { smem_u32(&hbuf[0][0][0]), smem_u32(&hbuf[1][0][0]) };
    const uint32_t hb[2] = { ab[0], ab[1] };

    float cst = 0.0f, hout = 0.0f;
    const size_t xw_dir = (size_t)dir * ((size_t)Tt * Bb * FOURH);
    const uint32_t hoff32 = (uint32_t)(bl * HSTR + j * 4);         // (hhi,hlo)
    const uint32_t hoff16 = (uint32_t)(bl * HSTR + 512 + j * 2);   // hhi block

    for (int t = 0; t < Tt; t++) {
        const int tt = dir ? (Tt - 1 - t) : t;
        const int p = t & 1;

        // xw prefetch before the wait
        const float* xwp = g_xw + xw_dir + ((size_t)tt * Bb + b) * FOURH;
        const float x0 = __ldg(xwp + j);
        const float x1 = __ldg(xwp + Hh + j);
        const float x2 = __ldg(xwp + 2 * Hh + j);
        const float x3 = __ldg(xwp + 3 * Hh + j);

        if (t > 0) CLUSTER_WAIT();

        // z = h @ U via tensor cores; 2 chains per tile to break latency
        float cA[2][4], cB[2][4];
#pragma unroll
        for (int i = 0; i < 2; i++)
#pragma unroll
            for (int q = 0; q < 4; q++) { cA[i][q] = 0.0f; cB[i][q] = 0.0f; }

        const uint32_t abase = ab[p] + rowoff;
#pragma unroll
        for (int ks = 0; ks < NKS; ks++) {
            uint32_t a[4];
            LDSM_X4(a[0], a[1], a[2], a[3], abase + (uint32_t)(32 * ks));
            if (ks & 1) {
                MMA16816(cB[0], a, breg[ks][0][0], breg[ks][0][1]);
                MMA16816(cB[1], a, breg[ks][1][0], breg[ks][1][1]);
            } else {
                MMA16816(cA[0], a, breg[ks][0][0], breg[ks][0][1]);
                MMA16816(cA[1], a, breg[ks][1][0], breg[ks][1][1]);
            }
        }
        // write valid rows (0..7) of both n8 tiles to z_sm
        *(float2*)&z_sm[nq][w * 16 + 2 * kq] =
            make_float2(cA[0][0] + cB[0][0], cA[0][1] + cB[0][1]);
        *(float2*)&z_sm[nq][w * 16 + 8 + 2 * kq] =
            make_float2(cA[1][0] + cB[1][0], cA[1][1] + cB[1][1]);
        __syncthreads();

        // gates: thread = unit ju x row bl
        const float a0 = z_sm[bl][ju]        + x0 + bz0;
        const float a1 = z_sm[bl][32 + ju]   + x1 + bz1;
        const float a2 = z_sm[bl][64 + ju]   + x2 + bz2;
        const float a3 = z_sm[bl][96 + ju]   + x3 + bz3;
        {
            const float ig = sigmoid_f(a0), fg = sigmoid_f(a1);
            const float gg = tanh_f(a2),    og = sigmoid_f(a3);
            cst = fg * cst + ig * gg;
            hout = og * tanh_f(cst);
        }

        // publish h (bf16 hi/lo) into buffer p^1 of all 4 cluster CTAs
        {
            const unsigned short hh = bfu(hout);
            const unsigned short hl = bfu(hout - bff(hh));
            const uint32_t v32 = (uint32_t)hh | ((uint32_t)hl << 16);
            const uint32_t base = hb[p ^ 1];
#pragma unroll
            for (int r = 0; r < 4; r++) {
                st_cluster_u32(base + hoff32, r, v32);
                st_cluster_u16(base + hoff16, r, hh);
            }
        }
        if (t < Tt - 1) CLUSTER_ARRIVE();
        out[((size_t)b * Tt + tt) * 256 + dir * Hh + j] = hout;
    }

    const size_t fin = (size_t)Bb * Tt * 256 + (size_t)dir * 2 * Bb * Hh;
    out[fin + (size_t)b * Hh + j]           = hout;
    out[fin + Bb * Hh + (size_t)b * Hh + j] = cst;

    CLUSTER_SYNC();
}

// ---------------- launch ----------------
extern "C" void kernel_launch(void* const* d_in, const int* in_sizes, int n_in,
                              void* d_out, int out_size) {
    const int*   tokens = (const int*)d_in[0];
    const float* emb    = (const float*)d_in[1];
    const float* Wfw    = (const float*)d_in[2];
    const float* Ufw    = (const float*)d_in[3];
    const float* bfw    = (const float*)d_in[4];
    const float* Wbw    = (const float*)d_in[5];
    const float* Ubw    = (const float*)d_in[6];
    const float* bbw    = (const float*)d_in[7];
    float* out = (float*)d_out;

    conv_emb<<<(Vv * Ee + 255) / 256, 256>>>(emb);
    conv_w<<<(2 * KP * FOURH + 255) / 256, 256>>>(Wfw, Wbw);
    proj_mma<<<dim3(4, 512, 2), 256>>>(tokens);
    lstm_kernel<<<128, 256>>>(Ufw, Ubw, bfw, bbw, out);
}

// round 12
// speedup vs baseline: 1.6816x; 1.0014x over previous
#include <cuda_runtime.h>
#include <cuda_bf16.h>
#include <cstdint>
#include <math.h>

#define Bb 128
#define Tt 512
#define Ee 256
#define Hh 128
#define FOURH 512
#define Vv 32000
#define KP 768

typedef unsigned long long u64t;
typedef __nv_bfloat16 bf16;

// ---------------- static scratch ----------------
__device__ float g_xw[(size_t)2 * Tt * Bb * FOURH];      // [dir][t*128+b][4H]
__device__ __align__(16) bf16 g_ehi[(size_t)Vv * Ee];
__device__ __align__(16) bf16 g_elo[(size_t)Vv * Ee];
__device__ __align__(16) bf16 g_Wt[2][KP][FOURH];        // [dir][k'][n]

// ---------------- helpers ----------------
__device__ __forceinline__ float sigmoid_f(float x) { return __fdividef(1.0f, 1.0f + __expf(-x)); }
__device__ __forceinline__ float tanh_f(float x)    { return __fdividef(2.0f, 1.0f + __expf(-2.0f * x)) - 1.0f; }
__device__ __forceinline__ uint32_t smem_u32(const void* p) {
    uint32_t a;
    asm("{ .reg .u64 t; cvta.to.shared.u64 t, %1; cvt.u32.u64 %0, t; }" : "=r"(a) : "l"(p));
    return a;
}
__device__ __forceinline__ void st_cluster_u32(uint32_t laddr, int rank, uint32_t v) {
    asm volatile(
        "{ .reg .b32 ra; mapa.shared::cluster.u32 ra, %0, %1; "
        "st.shared::cluster.b32 [ra], %2; }"
        :: "r"(laddr), "r"(rank), "r"(v) : "memory");
}
__device__ __forceinline__ void st_cluster_u16(uint32_t laddr, int rank, unsigned short v) {
    asm volatile(
        "{ .reg .b32 ra; mapa.shared::cluster.u32 ra, %0, %1; "
        "st.shared::cluster.b16 [ra], %2; }"
        :: "r"(laddr), "r"(rank), "h"(v) : "memory");
}
#define CLUSTER_ARRIVE() asm volatile("barrier.cluster.arrive.aligned;" ::: "memory")
#define CLUSTER_WAIT()   asm volatile("barrier.cluster.wait.aligned;" ::: "memory")
#define CLUSTER_SYNC() do { CLUSTER_ARRIVE(); CLUSTER_WAIT(); } while (0)

#define LDSM_X4(r0, r1, r2, r3, addr) \
    asm volatile("ldmatrix.sync.aligned.m8n8.x4.shared.b16 {%0,%1,%2,%3}, [%4];" \
                 : "=r"(r0), "=r"(r1), "=r"(r2), "=r"(r3) : "r"(addr))
#define LDSM_X4T(r0, r1, r2, r3, addr) \
    asm volatile("ldmatrix.sync.aligned.m8n8.x4.trans.shared.b16 {%0,%1,%2,%3}, [%4];" \
                 : "=r"(r0), "=r"(r1), "=r"(r2), "=r"(r3) : "r"(addr))
#define MMA16816(c, a, b0, b1) \
    asm volatile("mma.sync.aligned.m16n8k16.row.col.f32.bf16.bf16.f32 " \
                 "{%0,%1,%2,%3}, {%4,%5,%6,%7}, {%8,%9}, {%0,%1,%2,%3};" \
                 : "+f"((c)[0]), "+f"((c)[1]), "+f"((c)[2]), "+f"((c)[3]) \
                 : "r"((a)[0]), "r"((a)[1]), "r"((a)[2]), "r"((a)[3]), "r"(b0), "r"(b1))

__device__ __forceinline__ unsigned short bfu(float x) {
    bf16 h = __float2bfloat16(x);
    return __bfloat16_as_ushort(h);
}
__device__ __forceinline__ float bff(unsigned short u) {
    return __bfloat162float(__ushort_as_bfloat16(u));
}

// ---------------- conversion kernels ----------------
__global__ void conv_emb(const float* __restrict__ emb) {
    size_t i = (size_t)blockIdx.x * 256 + threadIdx.x;
    if (i < (size_t)Vv * Ee) {
        float x = emb[i];
        bf16 h = __float2bfloat16(x);
        g_ehi[i] = h;
        g_elo[i] = __float2bfloat16(x - __bfloat162float(h));
    }
}
__global__ void conv_w(const float* __restrict__ Wfw, const float* __restrict__ Wbw) {
    int i = blockIdx.x * 256 + threadIdx.x;
    if (i < 2 * KP * FOURH) {
        int d  = i / (KP * FOURH);
        int r  = i % (KP * FOURH);
        int kp = r / FOURH, n = r % FOURH;
        const float* W = d ? Wbw : Wfw;
        float x = W[(size_t)(kp & 255) * FOURH + n];
        bf16 hv = __float2bfloat16(x);
        g_Wt[d][kp][n] = (kp >= 256 && kp < 512)
                             ? __float2bfloat16(x - __bfloat162float(hv)) : hv;
    }
}

// ---------------- mma.sync projection GEMM (unchanged) ----------------
#define ASTR 40
#define BSTR 136

__global__ __launch_bounds__(256)
void proj_mma(const int* __restrict__ tokens) {
    __shared__ __align__(16) bf16 A_sm[128 * ASTR];
    __shared__ __align__(16) bf16 B_sm[32 * BSTR];
    __shared__ int tok[128];

    const int tid = threadIdx.x;
    const int wid = tid >> 5, lane = tid & 31;
    const int wm = wid & 3, wn = wid >> 2;
    const int n0 = blockIdx.x * 128;
    const int m0 = blockIdx.y * 128;
    const int dir = blockIdx.z;

    if (tid < 128) {
        int row = m0 + tid;
        tok[tid] = tokens[(row & 127) * Tt + (row >> 7)];
    }
    const uint32_t sbA = smem_u32(A_sm);
    const uint32_t sbB = smem_u32(B_sm);

    float c[2][8][4];
#pragma unroll
    for (int i = 0; i < 2; i++)
#pragma unroll
        for (int j = 0; j < 8; j++)
#pragma unroll
            for (int q = 0; q < 4; q++) c[i][j][q] = 0.0f;

    __syncthreads();

    for (int kt = 0; kt < 24; kt++) {
        const int kp0 = kt * 32;
        const bf16* __restrict__ Asrc = (kp0 < 512) ? g_ehi : g_elo;
        const int kb = kp0 & 255;

        uint4 av[2], bv[2];
#pragma unroll
        for (int u = 0; u < 2; u++) {
            const int q = tid + u * 256;
            const int arow = q >> 2, ac8 = q & 3;
            av[u] = *(const uint4*)(Asrc + (size_t)tok[arow] * Ee + kb + ac8 * 8);
            const int brow = q >> 4, bn8 = q & 15;
            bv[u] = *(const uint4*)(&g_Wt[dir][kp0 + brow][n0 + bn8 * 8]);
        }
        __syncthreads();
#pragma unroll
        for (int u = 0; u < 2; u++) {
            const int q = tid + u * 256;
            const int arow = q >> 2, ac8 = q & 3;
            *(uint4*)(A_sm + arow * ASTR + ac8 * 8) = av[u];
            const int brow = q >> 4, bn8 = q & 15;
            *(uint4*)(B_sm + brow * BSTR + bn8 * 8) = bv[u];
        }
        __syncthreads();

#pragma unroll
        for (int ks = 0; ks < 2; ks++) {
            uint32_t a[2][4];
#pragma unroll
            for (int i = 0; i < 2; i++) {
                const int m = wm * 32 + i * 16 + (lane & 7) + ((lane >> 3) & 1) * 8;
                const int kc = ks * 16 + (lane >> 4) * 8;
                LDSM_X4(a[i][0], a[i][1], a[i][2], a[i][3],
                        sbA + (uint32_t)(m * ASTR + kc) * 2);
            }
            uint32_t b[4][4];
#pragma unroll
            for (int j2 = 0; j2 < 4; j2++) {
                const int k = ks * 16 + (lane & 7) + ((lane >> 3) & 1) * 8;
                const int n = wn * 64 + j2 * 16 + (lane >> 4) * 8;
                LDSM_X4T(b[j2][0], b[j2][1], b[j2][2], b[j2][3],
                         sbB + (uint32_t)(k * BSTR + n) * 2);
            }
#pragma unroll
            for (int i = 0; i < 2; i++)
#pragma unroll
                for (int j = 0; j < 8; j++)
                    MMA16816(c[i][j], a[i], b[j >> 1][(j & 1) * 2], b[j >> 1][(j & 1) * 2 + 1]);
        }
    }

    const int g = lane >> 2, t2 = (lane & 3) * 2;
    float* const base = g_xw + (size_t)dir * Tt * Bb * FOURH;
#pragma unroll
    for (int i = 0; i < 2; i++) {
        const int mrow = m0 + wm * 32 + i * 16 + g;
#pragma unroll
        for (int j = 0; j < 8; j++) {
            const int col = n0 + wn * 64 + j * 8 + t2;
            float* d0 = base + (size_t)mrow * FOURH + col;
            d0[0] = c[i][j][0]; d0[1] = c[i][j][1];
            float* d1 = d0 + 8 * FOURH;
            d1[0] = c[i][j][2]; d1[1] = c[i][j][3];
        }
    }
}

// ---------------- persistent LSTM: tensor-core recurrence ----------------
// 128 CTAs, cluster(4) = one (dir,btile). CTA: 8 batch rows x 32 units
// (128 gatecols). Per step: z = h_pad[16,384] @ Ureg[384,128] via mma.sync,
// U held in registers (hi/lo split, K' = [ (hhi,hlo) x Uhi | hhi x Ulo ]).
// h exchanged via DSMEM in bf16 A-layout; R10 arrive/wait cluster protocol.
#define HSTR 784              // A row stride bytes (768 data + 16 pad)
#define NKS 24                // K' = 384 -> 24 k16 steps

__global__ __launch_bounds__(256, 1) __cluster_dims__(4, 1, 1)
void lstm_kernel(const float* __restrict__ Ufw, const float* __restrict__ Ubw,
                 const float* __restrict__ bfw, const float* __restrict__ bbw,
                 float* __restrict__ out) {
    __shared__ float z_sm[8][132];
    __shared__ __align__(16) char hbuf[2][16][HSTR];

    const int bx = blockIdx.x;
    const int dir = bx >> 6, id = bx & 63;
    const int btile = id >> 2, utile = id & 3;
    const int tid = threadIdx.x;
    const int w = tid >> 5, lane = tid & 31;
    const int kq = lane & 3, nq = lane >> 2;
    const int ju = tid >> 3, bl = tid & 7;
    const int j = utile * 32 + ju;          // global unit 0..127
    const int b = btile * 8 + bl;           // global batch row

    const float* __restrict__ U    = dir ? Ubw : Ufw;
    const float* __restrict__ bias = dir ? bbw : bfw;

    // ---- B fragments in registers: breg[ks][tile][2] ----
    uint32_t breg[NKS][2][2];
#pragma unroll
    for (int tile = 0; tile < 2; tile++) {
        const int nloc = w * 16 + tile * 8 + nq;                  // 0..127
        const int gcol = (nloc >> 5) * Hh + utile * 32 + (nloc & 31);
#pragma unroll
        for (int ks = 0; ks < 16; ks++) {      // (hhi,hlo) x dup(Uhi)
            const int u0 = 8 * ks + kq;
            const unsigned short h0 = bfu(U[(size_t)u0 * FOURH + gcol]);
            const unsigned short h1 = bfu(U[(size_t)(u0 + 4) * FOURH + gcol]);
            breg[ks][tile][0] = (uint32_t)h0 | ((uint32_t)h0 << 16);
            breg[ks][tile][1] = (uint32_t)h1 | ((uint32_t)h1 << 16);
        }
#pragma unroll
        for (int ks = 16; ks < NKS; ks++) {    // hhi x Ulo
            const int u0 = 16 * (ks - 16) + 2 * kq;
#pragma unroll
            for (int rr = 0; rr < 2; rr++) {
                const int ua = u0 + rr * 8, ub = ua + 1;
                float va = U[(size_t)ua * FOURH + gcol];
                float vb = U[(size_t)ub * FOURH + gcol];
                unsigned short la = bfu(va - bff(bfu(va)));
                unsigned short lb = bfu(vb - bff(bfu(vb)));
                breg[ks][tile][rr] = (uint32_t)la | ((uint32_t)lb << 16);
            }
        }
    }

    // zero both h buffers (incl. pad rows 8..15, which stay zero)
    for (int q = tid; q < (int)(2 * 16 * HSTR / 4); q += 256)
        ((uint32_t*)hbuf)[q] = 0u;

    const float bz0 = bias[j];
    const float bz1 = bias[Hh + j];
    const float bz2 = bias[2 * Hh + j];
    const float bz3 = bias[3 * Hh + j];

    __syncthreads();
    CLUSTER_SYNC();

    // ldmatrix per-lane source offset within a buffer
    const int arow = (lane & 7) + ((lane >> 3) & 1) * 8;
    const uint32_t rowoff = (uint32_t)(arow * HSTR + (lane >> 4) * 16);
    const uint32_t ab[2] = { smem_u32(&hbuf[0][0][0]), smem_u32(&hbuf[1][0][0]) };
    const uint32_t hb[2] = { ab[0], ab[1] };

    float cst = 0.0f, hout = 0.0f;
    const size_t xw_dir = (size_t)dir * ((size_t)Tt * Bb * FOURH);
    const uint32_t hoff32 = (uint32_t)(bl * HSTR + j * 4);         // (hhi,hlo)
    const uint32_t hoff16 = (uint32_t)(bl * HSTR + 512 + j * 2);   // hhi block

    for (int t = 0; t < Tt; t++) {
        const int tt = dir ? (Tt - 1 - t) : t;
        const int p = t & 1;

        // xw prefetch before the wait
        const float* xwp = g_xw + xw_dir + ((size_t)tt * Bb + b) * FOURH;
        const float x0 = __ldg(xwp + j);
        const float x1 = __ldg(xwp + Hh + j);
        const float x2 = __ldg(xwp + 2 * Hh + j);
        const float x3 = __ldg(xwp + 3 * Hh + j);

        if (t > 0) CLUSTER_WAIT();

        // z = h @ U via tensor cores; 2 chains per tile to break latency
        float cA[2][4], cB[2][4];
#pragma unroll
        for (int i = 0; i < 2; i++)
#pragma unroll
            for (int q = 0; q < 4; q++) { cA[i][q] = 0.0f; cB[i][q] = 0.0f; }

        const uint32_t abase = ab[p] + rowoff;
#pragma unroll
        for (int ks = 0; ks < NKS; ks++) {
            uint32_t a[4];
            LDSM_X4(a[0], a[1], a[2], a[3], abase + (uint32_t)(32 * ks));
            if (ks & 1) {
                MMA16816(cB[0], a, breg[ks][0][0], breg[ks][0][1]);
                MMA16816(cB[1], a, breg[ks][1][0], breg[ks][1][1]);
            } else {
                MMA16816(cA[0], a, breg[ks][0][0], breg[ks][0][1]);
                MMA16816(cA[1], a, breg[ks][1][0], breg[ks][1][1]);
            }
        }
        // write valid rows (0..7) of both n8 tiles to z_sm
        *(float2*)&z_sm[nq][w * 16 + 2 * kq] =
            make_float2(cA[0][0] + cB[0][0], cA[0][1] + cB[0][1]);
        *(float2*)&z_sm[nq][w * 16 + 8 + 2 * kq] =
            make_float2(cA[1][0] + cB[1][0], cA[1][1] + cB[1][1]);
        __syncthreads();

        // gates: thread = unit ju x row bl
        const float a0 = z_sm[bl][ju]        + x0 + bz0;
        const float a1 = z_sm[bl][32 + ju]   + x1 + bz1;
        const float a2 = z_sm[bl][64 + ju]   + x2 + bz2;
        const float a3 = z_sm[bl][96 + ju]   + x3 + bz3;
        {
            const float ig = sigmoid_f(a0), fg = sigmoid_f(a1);
            const float gg = tanh_f(a2),    og = sigmoid_f(a3);
            cst = fg * cst + ig * gg;
            hout = og * tanh_f(cst);
        }

        // publish h (bf16 hi/lo) into buffer p^1 of all 4 cluster CTAs
        {
            const unsigned short hh = bfu(hout);
            const unsigned short hl = bfu(hout - bff(hh));
            const uint32_t v32 = (uint32_t)hh | ((uint32_t)hl << 16);
            const uint32_t base = hb[p ^ 1];
#pragma unroll
            for (int r = 0; r < 4; r++) {
                st_cluster_u32(base + hoff32, r, v32);
                st_cluster_u16(base + hoff16, r, hh);
            }
        }
        if (t < Tt - 1) CLUSTER_ARRIVE();
        out[((size_t)b * Tt + tt) * 256 + dir * Hh + j] = hout;
    }

    const size_t fin = (size_t)Bb * Tt * 256 + (size_t)dir * 2 * Bb * Hh;
    out[fin + (size_t)b * Hh + j]           = hout;
    out[fin + Bb * Hh + (size_t)b * Hh + j] = cst;

    CLUSTER_SYNC();
}

// ---------------- launch ----------------
extern "C" void kernel_launch(void* const* d_in, const int* in_sizes, int n_in,
                              void* d_out, int out_size) {
    const int*   tokens = (const int*)d_in[0];
    const float* emb    = (const float*)d_in[1];
    const float* Wfw    = (const float*)d_in[2];
    const float* Ufw    = (const float*)d_in[3];
    const float* bfw    = (const float*)d_in[4];
    const float* Wbw    = (const float*)d_in[5];
    const float* Ubw    = (const float*)d_in[6];
    const float* bbw    = (const float*)d_in[7];
    float* out = (float*)d_out;

    conv_emb<<<(Vv * Ee + 255) / 256, 256>>>(emb);
    conv_w<<<(2 * KP * FOURH + 255) / 256, 256>>>(Wfw, Wbw);
    proj_mma<<<dim3(4, 512, 2), 256>>>(tokens);
    lstm_kernel<<<128, 256>>>(Ufw, Ubw, bfw, bbw, out);
}